// round 15
// baseline (speedup 1.0000x reference)
#include <cuda_runtime.h>
#include <cuda_bf16.h>
#include <math.h>

#define MAXN 100000
#define MAXE 1600000
#define MAXG 500
#define LL 8
#define BN_EPS 1e-5f

// ---------------- device scratch ----------------
__device__ __nv_bfloat162 g_hh[2][(size_t)MAXN * 32];  // bf16 features, ping-pong (128B rows)
__device__ uint4 g_zhi[(size_t)MAXN * 8];               // z hi split, 32 u32/node
__device__ uint4 g_zlo[(size_t)MAXN * 8];               // z lo split
__device__ float g_agg1[MAXN];                          // layer-0 scalar agg
__device__ float g_pooled[(size_t)MAXG * LL * 64];
__device__ unsigned g_wprep[7 * 9216];                  // split-transposed weights, smem layout
__device__ unsigned g_w0prep[4608];                     // layer-0 W2 split (hi|lo)
__device__ int g_deg[MAXN + 1];
__device__ int g_off[MAXN + 2];
__device__ int g_pos[MAXN + 1];
__device__ int g_csr[MAXE];
// decoupled-lookback scan state
__device__ int g_ticket;
__device__ volatile int g_tileflag[128];
__device__ volatile int g_tileagg[128];
__device__ volatile int g_tilepref[128];

// ---------------- helpers ----------------
__device__ __forceinline__ void bfsplit(float x, float y, unsigned& hi, unsigned& lo) {
    __nv_bfloat162 h = __floats2bfloat162_rn(x, y);
    float rx = x - __bfloat162float(h.x);
    float ry = y - __bfloat162float(h.y);
    __nv_bfloat162 l = __floats2bfloat162_rn(rx, ry);
    hi = *reinterpret_cast<unsigned*>(&h);
    lo = *reinterpret_cast<unsigned*>(&l);
}
__device__ __forceinline__ void mma16(float (&c)[4], unsigned a0, unsigned a1, unsigned a2, unsigned a3,
                                      unsigned b0, unsigned b1) {
    asm volatile("mma.sync.aligned.m16n8k16.row.col.f32.bf16.bf16.f32 "
                 "{%0,%1,%2,%3},{%4,%5,%6,%7},{%8,%9},{%0,%1,%2,%3};"
                 : "+f"(c[0]), "+f"(c[1]), "+f"(c[2]), "+f"(c[3])
                 : "r"(a0), "r"(a1), "r"(a2), "r"(a3), "r"(b0), "r"(b1));
}

// ============ CSR build ============
__global__ __launch_bounds__(256) void deg_count(const int* __restrict__ ei, int E, int* __restrict__ deg) {
    int e = blockIdx.x * 256 + threadIdx.x;
    if (e >= E) return;
    atomicAdd(&deg[ei[E + e]], 1);
}

// single-pass exclusive scan with decoupled lookback (atomic-ticket ordered)
__global__ __launch_bounds__(1024) void scan_lookback(const int* __restrict__ deg, int n,
                                                      int* __restrict__ off, int* __restrict__ pos) {
    __shared__ int sh[1024];
    __shared__ int s_tile;
    __shared__ int s_prefix;
    int t = threadIdx.x;
    if (t == 0) s_tile = atomicAdd(&g_ticket, 1);
    __syncthreads();
    int tile = s_tile;
    int i = tile * 1024 + t;
    int v = (i < n) ? deg[i] : 0;
    sh[t] = v;
    __syncthreads();
    for (int d = 1; d < 1024; d <<= 1) {
        int add = (t >= d) ? sh[t - d] : 0;
        __syncthreads();
        sh[t] += add;
        __syncthreads();
    }
    if (t == 1023) {
        int total = sh[1023];
        if (tile == 0) {
            g_tilepref[0] = total;
            __threadfence();
            g_tileflag[0] = 2;
            s_prefix = 0;
        } else {
            g_tileagg[tile] = total;
            __threadfence();
            g_tileflag[tile] = 1;
            int run = 0;
            int j = tile - 1;
            while (true) {
                int f;
                do { f = g_tileflag[j]; } while (f == 0);
                __threadfence();
                if (f == 2) { run += g_tilepref[j]; break; }
                run += g_tileagg[j];
                --j;
            }
            g_tilepref[tile] = run + total;
            __threadfence();
            g_tileflag[tile] = 2;
            s_prefix = run;
        }
    }
    __syncthreads();
    if (i < n) {
        int ex = sh[t] - v + s_prefix;
        off[i] = ex;
        pos[i] = ex;
    }
}

__global__ __launch_bounds__(256) void csr_scatter(const int* __restrict__ ei, int E,
                                                   int* __restrict__ pos, int* __restrict__ csr) {
    int e = blockIdx.x * 256 + threadIdx.x;
    if (e >= E) return;
    int src = ei[e];
    int dst = ei[E + e];
    int p = atomicAdd(&pos[dst], 1);
    csr[p] = src;
}

// ============ weight pre-transform (once per launch) ============
#define AS 36   // row pitch in u32 (32 data + 4 pad)

__global__ __launch_bounds__(128) void prep_weights(const float* __restrict__ W1r,
                                                    const float* __restrict__ W2all,
                                                    unsigned* __restrict__ wprep) {
    int layer = blockIdx.x;                    // 0..6 -> layers 1..7
    const float* W1 = W1r + (size_t)layer * 4096;
    const float* W2 = W2all + (size_t)(layer + 1) * 4096;
    unsigned* dst = wprep + (size_t)layer * 9216;
    for (int idx = threadIdx.x; idx < 2048; idx += 128) {
        int n = idx >> 5, k2 = idx & 31;
        int koff = k2 * 128 + n;
        unsigned hi, lo;
        bfsplit(W1[koff], W1[koff + 64], hi, lo);
        dst[n * AS + k2] = hi;
        dst[2304 + n * AS + k2] = lo;
        bfsplit(W2[koff], W2[koff + 64], hi, lo);
        dst[4608 + n * AS + k2] = hi;
        dst[6912 + n * AS + k2] = lo;
    }
}

__global__ __launch_bounds__(128) void prep_w0(const float* __restrict__ W2all,
                                               unsigned* __restrict__ w0prep) {
    const float* W2 = W2all;   // layer 0
    for (int idx = threadIdx.x; idx < 2048; idx += 128) {
        int n = idx >> 5, k2 = idx & 31;
        int koff = k2 * 128 + n;
        unsigned hi, lo;
        bfsplit(W2[koff], W2[koff + 64], hi, lo);
        w0prep[n * AS + k2] = hi;
        w0prep[2304 + n * AS + k2] = lo;
    }
}

// ============ CSR aggregation (bf16 rows -> split-bf16 z) ============
__device__ __forceinline__ void addrow_u(uint4 v, float* acc) {
    acc[0] += __uint_as_float(v.x << 16);
    acc[1] += __uint_as_float(v.x & 0xffff0000u);
    acc[2] += __uint_as_float(v.y << 16);
    acc[3] += __uint_as_float(v.y & 0xffff0000u);
    acc[4] += __uint_as_float(v.z << 16);
    acc[5] += __uint_as_float(v.z & 0xffff0000u);
    acc[6] += __uint_as_float(v.w << 16);
    acc[7] += __uint_as_float(v.w & 0xffff0000u);
}

// 8 threads per node, each thread covers 8 contiguous features (16B).
__global__ __launch_bounds__(256) void csr_agg_h(const int* __restrict__ off, const int* __restrict__ csr,
                                                 const __nv_bfloat162* __restrict__ hh,
                                                 uint4* __restrict__ zhi_g, uint4* __restrict__ zlo_g,
                                                 const float* __restrict__ eps, int N) {
    int t = blockIdx.x * 256 + threadIdx.x;
    int n = t >> 3;
    if (n >= N) return;
    int q = t & 7;
    const uint4* hq = reinterpret_cast<const uint4*>(hh) + q;
    float acc[8];
#pragma unroll
    for (int j = 0; j < 8; ++j) acc[j] = 0.f;
    int b = off[n], e = off[n + 1];
    int i = b;
    for (; i + 8 <= e; i += 8) {
        int idx[8];
#pragma unroll
        for (int u = 0; u < 8; ++u) idx[u] = __ldg(&csr[i + u]);
        uint4 v[8];
#pragma unroll
        for (int u = 0; u < 8; ++u) v[u] = hq[idx[u] * 8];
#pragma unroll
        for (int u = 0; u < 8; ++u) addrow_u(v[u], acc);
    }
    for (; i + 4 <= e; i += 4) {
        int i0 = __ldg(&csr[i]);
        int i1 = __ldg(&csr[i + 1]);
        int i2 = __ldg(&csr[i + 2]);
        int i3 = __ldg(&csr[i + 3]);
        uint4 v0 = hq[i0 * 8];
        uint4 v1 = hq[i1 * 8];
        uint4 v2 = hq[i2 * 8];
        uint4 v3 = hq[i3 * 8];
        addrow_u(v0, acc);
        addrow_u(v1, acc);
        addrow_u(v2, acc);
        addrow_u(v3, acc);
    }
    for (; i < e; ++i) addrow_u(hq[__ldg(&csr[i]) * 8], acc);

    float ev = 1.0f + eps[0];
    uint4 sv = hq[n * 8];
    float o[8];
    o[0] = fmaf(ev, __uint_as_float(sv.x << 16),          acc[0]);
    o[1] = fmaf(ev, __uint_as_float(sv.x & 0xffff0000u),  acc[1]);
    o[2] = fmaf(ev, __uint_as_float(sv.y << 16),          acc[2]);
    o[3] = fmaf(ev, __uint_as_float(sv.y & 0xffff0000u),  acc[3]);
    o[4] = fmaf(ev, __uint_as_float(sv.z << 16),          acc[4]);
    o[5] = fmaf(ev, __uint_as_float(sv.z & 0xffff0000u),  acc[5]);
    o[6] = fmaf(ev, __uint_as_float(sv.w << 16),          acc[6]);
    o[7] = fmaf(ev, __uint_as_float(sv.w & 0xffff0000u),  acc[7]);

    uint4 hi4, lo4;
    bfsplit(o[0], o[1], hi4.x, lo4.x);
    bfsplit(o[2], o[3], hi4.y, lo4.y);
    bfsplit(o[4], o[5], hi4.z, lo4.z);
    bfsplit(o[6], o[7], hi4.w, lo4.w);
    zhi_g[(size_t)n * 8 + q] = hi4;
    zlo_g[(size_t)n * 8 + q] = lo4;
}

// scalar features (layer 0)
__global__ __launch_bounds__(256) void csr_agg1(const int* __restrict__ off, const int* __restrict__ csr,
                                                const float* __restrict__ x, float* __restrict__ agg, int N) {
    int n = blockIdx.x * 256 + threadIdx.x;
    if (n >= N) return;
    int b = off[n], e = off[n + 1];
    float s = 0.f;
    int i = b;
    for (; i + 4 <= e; i += 4) {
        float v0 = x[__ldg(&csr[i])];
        float v1 = x[__ldg(&csr[i + 1])];
        float v2 = x[__ldg(&csr[i + 2])];
        float v3 = x[__ldg(&csr[i + 3])];
        s += (v0 + v1) + (v2 + v3);
    }
    for (; i < e; ++i) s += x[__ldg(&csr[i])];
    agg[n] = s;
}

// layer 0 MLP1+BN1: 8 threads/node, thread q handles features [8q, 8q+8)
__global__ __launch_bounds__(256) void node0_prep(
        const float* __restrict__ x, const float* __restrict__ agg,
        uint4* __restrict__ zhi_g, uint4* __restrict__ zlo_g,
        const float* __restrict__ eps, const float* __restrict__ W1f,
        const float* __restrict__ b1, const float* __restrict__ g1,
        const float* __restrict__ be1, const float* __restrict__ m1,
        const float* __restrict__ v1, int N) {
    int t = blockIdx.x * 256 + threadIdx.x;
    int n = t >> 3;
    if (n >= N) return;
    int q = t & 7;
    float ev = 1.0f + eps[0];
    float z = fmaf(ev, x[n], agg[n]);
    float o[8];
#pragma unroll
    for (int u = 0; u < 8; ++u) {
        int j = q * 8 + u;
        float s1 = __ldg(&g1[j]) * rsqrtf(__ldg(&v1[j]) + BN_EPS);
        float t1 = fmaf(-__ldg(&m1[j]), s1, __ldg(&be1[j]));
        float y = fmaxf(fmaf(z, __ldg(&W1f[j]), __ldg(&b1[j])), 0.f);
        o[u] = fmaf(y, s1, t1);
    }
    uint4 hi4, lo4;
    bfsplit(o[0], o[1], hi4.x, lo4.x);
    bfsplit(o[2], o[3], hi4.y, lo4.y);
    bfsplit(o[4], o[5], hi4.z, lo4.z);
    bfsplit(o[6], o[7], hi4.w, lo4.w);
    zhi_g[(size_t)n * 8 + q] = hi4;
    zlo_g[(size_t)n * 8 + q] = lo4;
}

// ============ BN params ============
__device__ __forceinline__ void load_bn_params(float* prm, int tid,
        const float* b1, const float* g1, const float* be1, const float* m1, const float* v1,
        const float* b2, const float* g2, const float* be2, const float* m2, const float* v2) {
    if (tid < 64) {
        float s1 = g1[tid] * rsqrtf(v1[tid] + BN_EPS);
        prm[tid]       = b1[tid];
        prm[64 + tid]  = s1;
        prm[128 + tid] = fmaf(-m1[tid], s1, be1[tid]);
        float s2 = g2[tid] * rsqrtf(v2[tid] + BN_EPS);
        prm[192 + tid] = b2[tid];
        prm[256 + tid] = s2;
        prm[320 + tid] = fmaf(-m2[tid], s2, be2[tid]);
    }
}

// ============ tensor-core node MLP, bf16x2 split 3-term, 256 nodes/block ============
#define OFF_W1HI 0
#define OFF_W1LO 2304
#define OFF_W2HI 4608
#define OFF_W2LO 6912
#define OFF_ZHI  9216
#define OFF_ZLO  18432
#define OFF_PRM  27648
#define MMA_SMEM_U32 (27648 + 384)

__device__ __forceinline__ void warp_gemm_bf(const unsigned* __restrict__ Whi,
                                             const unsigned* __restrict__ Wlo,
                                             const unsigned* __restrict__ zhi,
                                             const unsigned* __restrict__ zlo,
                                             int warp, int lane, float acc[2][8][4]) {
    int tig = lane & 3;
    int grp = lane >> 2;
#pragma unroll
    for (int kk = 0; kk < 4; ++kk) {
        int k2a = kk * 8 + tig;
        int k2b = kk * 8 + 4 + tig;
        unsigned bh[8][2], bl[8][2];
#pragma unroll
        for (int nt = 0; nt < 8; ++nt) {
            int n = nt * 8 + grp;
            bh[nt][0] = Whi[n * AS + k2a];
            bh[nt][1] = Whi[n * AS + k2b];
            bl[nt][0] = Wlo[n * AS + k2a];
            bl[nt][1] = Wlo[n * AS + k2b];
        }
#pragma unroll
        for (int mt = 0; mt < 2; ++mt) {
            int r0 = warp * 32 + mt * 16 + grp;
            unsigned ah0 = zhi[r0 * AS + k2a];
            unsigned ah1 = zhi[(r0 + 8) * AS + k2a];
            unsigned ah2 = zhi[r0 * AS + k2b];
            unsigned ah3 = zhi[(r0 + 8) * AS + k2b];
            unsigned al0 = zlo[r0 * AS + k2a];
            unsigned al1 = zlo[(r0 + 8) * AS + k2a];
            unsigned al2 = zlo[r0 * AS + k2b];
            unsigned al3 = zlo[(r0 + 8) * AS + k2b];
#pragma unroll
            for (int nt = 0; nt < 8; ++nt) {
                mma16(acc[mt][nt], ah0, ah1, ah2, ah3, bh[nt][0], bh[nt][1]);
                mma16(acc[mt][nt], ah0, ah1, ah2, ah3, bl[nt][0], bl[nt][1]);
                mma16(acc[mt][nt], al0, al1, al2, al3, bh[nt][0], bh[nt][1]);
            }
        }
    }
}

// shared epilogue: BN2 + bf16 store + pooled RED (warp-prereduced atomics)
__device__ __forceinline__ void mma_epilogue(float acc[2][8][4], const float* prm,
                                             const int* sh_b, int n0, int warp, int lane,
                                             int tig, int grp, int N, int layer,
                                             __nv_bfloat162* houth, float* pooled) {
    int gme = sh_b[warp * 32 + lane];
    int g0 = __shfl_sync(0xffffffffu, gme, 0);
    bool uni = __all_sync(0xffffffffu, gme == g0) && (g0 >= 0);

#pragma unroll
    for (int nt = 0; nt < 8; ++nt) {
        int j = nt * 8 + 2 * tig;
        float b2a = prm[192 + j], b2b = prm[192 + j + 1];
        float s2a = prm[256 + j], s2b = prm[256 + j + 1];
        float t2a = prm[320 + j], t2b = prm[320 + j + 1];
        int jc = j >> 1;
        float p0 = 0.f, p1 = 0.f;
#pragma unroll
        for (int mt = 0; mt < 2; ++mt) {
            float* C = acc[mt][nt];
            int row = warp * 32 + mt * 16 + grp;
            int n = n0 + row;
            if (n < N) {
                float o0 = fmaf(fmaxf(C[0] + b2a, 0.f), s2a, t2a);
                float o1 = fmaf(fmaxf(C[1] + b2b, 0.f), s2b, t2b);
                houth[(size_t)n * 32 + jc] = __floats2bfloat162_rn(o0, o1);
                if (uni) { p0 += o0; p1 += o1; }
                else {
                    float* pp = pooled + (size_t)sh_b[row] * 512 + layer * 64 + j;
                    atomicAdd(pp, o0);
                    atomicAdd(pp + 1, o1);
                }
            }
            if (n + 8 < N) {
                float o2 = fmaf(fmaxf(C[2] + b2a, 0.f), s2a, t2a);
                float o3 = fmaf(fmaxf(C[3] + b2b, 0.f), s2b, t2b);
                houth[(size_t)(n + 8) * 32 + jc] = __floats2bfloat162_rn(o2, o3);
                if (uni) { p0 += o2; p1 += o3; }
                else {
                    float* pp = pooled + (size_t)sh_b[row + 8] * 512 + layer * 64 + j;
                    atomicAdd(pp, o2);
                    atomicAdd(pp + 1, o3);
                }
            }
        }
        if (uni) {
            p0 += __shfl_xor_sync(0xffffffffu, p0, 4);
            p1 += __shfl_xor_sync(0xffffffffu, p1, 4);
            p0 += __shfl_xor_sync(0xffffffffu, p0, 8);
            p1 += __shfl_xor_sync(0xffffffffu, p1, 8);
            p0 += __shfl_xor_sync(0xffffffffu, p0, 16);
            p1 += __shfl_xor_sync(0xffffffffu, p1, 16);
            if (grp == 0) {
                float* pp = pooled + (size_t)g0 * 512 + layer * 64 + j;
                atomicAdd(pp, p0);
                atomicAdd(pp + 1, p1);
            }
        }
    }
}

__global__ __launch_bounds__(256) void gin_node_mma(
        const uint4* __restrict__ zhi_g, const uint4* __restrict__ zlo_g,
        __nv_bfloat162* __restrict__ houth,
        const int* __restrict__ batch, float* __restrict__ pooled, int layer,
        const unsigned* __restrict__ wprep,
        const float* __restrict__ b1,
        const float* __restrict__ g1, const float* __restrict__ be1,
        const float* __restrict__ m1, const float* __restrict__ v1,
        const float* __restrict__ b2,
        const float* __restrict__ g2, const float* __restrict__ be2,
        const float* __restrict__ m2, const float* __restrict__ v2, int N) {
    extern __shared__ unsigned smu[];
    unsigned* W1hi = smu + OFF_W1HI;
    unsigned* W1lo = smu + OFF_W1LO;
    unsigned* W2hi = smu + OFF_W2HI;
    unsigned* W2lo = smu + OFF_W2LO;
    unsigned* zhi  = smu + OFF_ZHI;
    unsigned* zlo  = smu + OFF_ZLO;
    float* prm = reinterpret_cast<float*>(smu + OFF_PRM);
    __shared__ int sh_b[256];
    int tid = threadIdx.x;
    int warp = tid >> 5, lane = tid & 31;
    int tig = lane & 3, grp = lane >> 2;

    {
        const uint4* wsrc = reinterpret_cast<const uint4*>(wprep);
        uint4* wdst = reinterpret_cast<uint4*>(smu);
#pragma unroll
        for (int i = tid; i < 2304; i += 256) wdst[i] = wsrc[i];
    }
    load_bn_params(prm, tid, b1, g1, be1, m1, v1, b2, g2, be2, m2, v2);

    int n0 = blockIdx.x * 256;
    sh_b[tid] = (n0 + tid < N) ? batch[n0 + tid] : -1;

    for (int i2 = tid; i2 < 2048; i2 += 256) {
        int row = i2 >> 3, qq = i2 & 7;
        uint4 h4 = make_uint4(0, 0, 0, 0), l4 = make_uint4(0, 0, 0, 0);
        if (n0 + row < N) {
            h4 = zhi_g[(size_t)n0 * 8 + i2];
            l4 = zlo_g[(size_t)n0 * 8 + i2];
        }
        *reinterpret_cast<uint4*>(&zhi[row * AS + qq * 4]) = h4;
        *reinterpret_cast<uint4*>(&zlo[row * AS + qq * 4]) = l4;
    }
    __syncthreads();

    float acc[2][8][4];
#pragma unroll
    for (int mt = 0; mt < 2; ++mt)
#pragma unroll
        for (int nt = 0; nt < 8; ++nt)
#pragma unroll
            for (int p = 0; p < 4; ++p) acc[mt][nt][p] = 0.f;

    warp_gemm_bf(W1hi, W1lo, zhi, zlo, warp, lane, acc);

    // BN1 + ReLU -> back into zs (warp-private rows), zero acc
#pragma unroll
    for (int nt = 0; nt < 8; ++nt) {
        int j = nt * 8 + 2 * tig;
        float b1a = prm[j],       b1b = prm[j + 1];
        float s1a = prm[64 + j],  s1b = prm[64 + j + 1];
        float t1a = prm[128 + j], t1b = prm[128 + j + 1];
        int k2 = nt * 4 + tig;
#pragma unroll
        for (int mt = 0; mt < 2; ++mt) {
            float* C = acc[mt][nt];
            int row = warp * 32 + mt * 16 + grp;
            float y0 = fmaf(fmaxf(C[0] + b1a, 0.f), s1a, t1a);
            float y1 = fmaf(fmaxf(C[1] + b1b, 0.f), s1b, t1b);
            float y2 = fmaf(fmaxf(C[2] + b1a, 0.f), s1a, t1a);
            float y3 = fmaf(fmaxf(C[3] + b1b, 0.f), s1b, t1b);
            unsigned hi, lo;
            bfsplit(y0, y1, hi, lo);
            zhi[row * AS + k2] = hi;
            zlo[row * AS + k2] = lo;
            bfsplit(y2, y3, hi, lo);
            zhi[(row + 8) * AS + k2] = hi;
            zlo[(row + 8) * AS + k2] = lo;
            C[0] = C[1] = C[2] = C[3] = 0.f;
        }
    }
    __syncwarp();

    warp_gemm_bf(W2hi, W2lo, zhi, zlo, warp, lane, acc);
    mma_epilogue(acc, prm, sh_b, n0, warp, lane, tig, grp, N, layer, houth, pooled);
}

// layer 0 node kernel: GEMM2-only (z buffers already hold BN1(ReLU(MLP1)))
__global__ __launch_bounds__(256) void gin_node0_mma(
        const uint4* __restrict__ zhi_g, const uint4* __restrict__ zlo_g,
        __nv_bfloat162* __restrict__ houth,
        const int* __restrict__ batch, float* __restrict__ pooled,
        const unsigned* __restrict__ w0prep,
        const float* __restrict__ b1,
        const float* __restrict__ g1, const float* __restrict__ be1,
        const float* __restrict__ m1, const float* __restrict__ v1,
        const float* __restrict__ b2,
        const float* __restrict__ g2, const float* __restrict__ be2,
        const float* __restrict__ m2, const float* __restrict__ v2, int N) {
    extern __shared__ unsigned smu[];
    unsigned* W2hi = smu + OFF_W2HI;
    unsigned* W2lo = smu + OFF_W2LO;
    unsigned* zhi  = smu + OFF_ZHI;
    unsigned* zlo  = smu + OFF_ZLO;
    float* prm = reinterpret_cast<float*>(smu + OFF_PRM);
    __shared__ int sh_b[256];
    int tid = threadIdx.x;
    int warp = tid >> 5, lane = tid & 31;
    int tig = lane & 3, grp = lane >> 2;

    {
        const uint4* wsrc = reinterpret_cast<const uint4*>(w0prep);
        uint4* wdst = reinterpret_cast<uint4*>(smu + OFF_W2HI);
#pragma unroll
        for (int i = tid; i < 1152; i += 256) wdst[i] = wsrc[i];
    }
    load_bn_params(prm, tid, b1, g1, be1, m1, v1, b2, g2, be2, m2, v2);

    int n0 = blockIdx.x * 256;
    sh_b[tid] = (n0 + tid < N) ? batch[n0 + tid] : -1;

    for (int i2 = tid; i2 < 2048; i2 += 256) {
        int row = i2 >> 3, qq = i2 & 7;
        uint4 h4 = make_uint4(0, 0, 0, 0), l4 = make_uint4(0, 0, 0, 0);
        if (n0 + row < N) {
            h4 = zhi_g[(size_t)n0 * 8 + i2];
            l4 = zlo_g[(size_t)n0 * 8 + i2];
        }
        *reinterpret_cast<uint4*>(&zhi[row * AS + qq * 4]) = h4;
        *reinterpret_cast<uint4*>(&zlo[row * AS + qq * 4]) = l4;
    }
    __syncthreads();

    float acc[2][8][4];
#pragma unroll
    for (int mt = 0; mt < 2; ++mt)
#pragma unroll
        for (int nt = 0; nt < 8; ++nt)
#pragma unroll
            for (int p = 0; p < 4; ++p) acc[mt][nt][p] = 0.f;

    warp_gemm_bf(W2hi, W2lo, zhi, zlo, warp, lane, acc);
    mma_epilogue(acc, prm, sh_b, n0, warp, lane, tig, grp, N, 0, houth, pooled);
}

// ---------------- classifier head ----------------
__device__ __forceinline__ int lbound(const int* __restrict__ a, int n, int v) {
    int lo = 0, hi = n;
    while (lo < hi) {
        int mid = (lo + hi) >> 1;
        if (a[mid] < v) lo = mid + 1; else hi = mid;
    }
    return lo;
}

__global__ __launch_bounds__(64) void classify_kernel(
        const float* __restrict__ pooled, const int* __restrict__ batch, int N,
        const float* __restrict__ lw1, const float* __restrict__ lb1,
        const float* __restrict__ lw2, const float* __restrict__ lb2,
        float* __restrict__ out) {
    __shared__ float ps[512];
    __shared__ float hid[64];
    __shared__ float lg[3];
    __shared__ float inv;
    int g = blockIdx.x;
    int tid = threadIdx.x;
    if (tid == 0) {
        int a = lbound(batch, N, g);
        int b = lbound(batch, N, g + 1);
        int c = b - a;
        inv = 1.0f / (float)(c > 1 ? c : 1);
    }
    __syncthreads();
    for (int k = tid; k < 512; k += 64) ps[k] = pooled[(size_t)g * 512 + k] * inv;
    __syncthreads();
    float acc = lb1[tid];
#pragma unroll 8
    for (int k = 0; k < 512; ++k) acc = fmaf(ps[k], lw1[k * 64 + tid], acc);
    hid[tid] = fmaxf(acc, 0.f);
    __syncthreads();
    if (tid < 3) {
        float s = lb2[tid];
#pragma unroll
        for (int j = 0; j < 64; ++j) s = fmaf(hid[j], lw2[j * 3 + tid], s);
        lg[tid] = s;
    }
    __syncthreads();
    if (tid == 0) {
        float m = fmaxf(lg[0], fmaxf(lg[1], lg[2]));
        float e = expf(lg[0] - m) + expf(lg[1] - m) + expf(lg[2] - m);
        float lse = m + logf(e);
        out[g * 3 + 0] = lg[0] - lse;
        out[g * 3 + 1] = lg[1] - lse;
        out[g * 3 + 2] = lg[2] - lse;
    }
}

// ---------------- launcher ----------------
extern "C" void kernel_launch(void* const* d_in, const int* in_sizes, int n_in,
                              void* d_out, int out_size) {
    const float* x     = (const float*)d_in[0];
    const int*   ei    = (const int*)d_in[1];
    const int*   batch = (const int*)d_in[2];
    int bi = (in_sizes[3] == 1) ? 4 : 3;
    const float* eps  = (const float*)d_in[bi + 0];
    const float* W1f  = (const float*)d_in[bi + 1];
    const float* W1r  = (const float*)d_in[bi + 2];
    const float* b1   = (const float*)d_in[bi + 3];
    const float* g1   = (const float*)d_in[bi + 4];
    const float* be1  = (const float*)d_in[bi + 5];
    const float* m1   = (const float*)d_in[bi + 6];
    const float* v1   = (const float*)d_in[bi + 7];
    const float* W2   = (const float*)d_in[bi + 8];
    const float* b2   = (const float*)d_in[bi + 9];
    const float* g2   = (const float*)d_in[bi + 10];
    const float* be2  = (const float*)d_in[bi + 11];
    const float* m2   = (const float*)d_in[bi + 12];
    const float* v2   = (const float*)d_in[bi + 13];
    const float* lw1  = (const float*)d_in[bi + 14];
    const float* lb1  = (const float*)d_in[bi + 15];
    const float* lw2  = (const float*)d_in[bi + 16];
    const float* lb2  = (const float*)d_in[bi + 17];

    int N = in_sizes[0];
    int E = in_sizes[1] / 2;
    int G = out_size / 3;
    if (N > MAXN) N = MAXN;
    if (E > MAXE) E = MAXE;
    if (G > MAXG) G = MAXG;

    __nv_bfloat162 *hh0, *hh1;
    uint4 *zhi_g, *zlo_g;
    float *agg1, *pooled;
    unsigned *wprep, *w0prep;
    int *deg, *off, *pos, *csr;
    int *ticket;
    void *flags;
    cudaGetSymbolAddress((void**)&hh0, g_hh);
    hh1 = hh0 + (size_t)MAXN * 32;
    cudaGetSymbolAddress((void**)&zhi_g, g_zhi);
    cudaGetSymbolAddress((void**)&zlo_g, g_zlo);
    cudaGetSymbolAddress((void**)&agg1, g_agg1);
    cudaGetSymbolAddress((void**)&pooled, g_pooled);
    cudaGetSymbolAddress((void**)&wprep, g_wprep);
    cudaGetSymbolAddress((void**)&w0prep, g_w0prep);
    cudaGetSymbolAddress((void**)&deg, g_deg);
    cudaGetSymbolAddress((void**)&off, g_off);
    cudaGetSymbolAddress((void**)&pos, g_pos);
    cudaGetSymbolAddress((void**)&csr, g_csr);
    cudaGetSymbolAddress((void**)&ticket, g_ticket);
    cudaGetSymbolAddress(&flags, g_tileflag);

    cudaFuncSetAttribute(gin_node_mma, cudaFuncAttributeMaxDynamicSharedMemorySize,
                         MMA_SMEM_U32 * 4);
    cudaFuncSetAttribute(gin_node0_mma, cudaFuncAttributeMaxDynamicSharedMemorySize,
                         MMA_SMEM_U32 * 4);

    int nodeGrid = (N + 255) / 256;
    int edgeGrid = (E + 255) / 256;
    int nScan = N + 1;
    int nTiles = (nScan + 1023) / 1024;

    // ----- CSR build + pooled clear + weight prep -----
    cudaMemsetAsync(deg, 0, (size_t)nScan * sizeof(int));
    cudaMemsetAsync(pooled, 0, (size_t)G * 512 * sizeof(float));
    cudaMemsetAsync(ticket, 0, sizeof(int));
    cudaMemsetAsync(flags, 0, 128 * sizeof(int));
    prep_weights<<<7, 128>>>(W1r, W2, wprep);
    prep_w0<<<1, 128>>>(W2, w0prep);
    deg_count<<<edgeGrid, 256>>>(ei, E, deg);
    scan_lookback<<<nTiles, 1024>>>(deg, nScan, off, pos);
    csr_scatter<<<edgeGrid, 256>>>(ei, E, pos, csr);

    // ----- layer 0 (scalar input) -----
    csr_agg1<<<(N + 255) / 256, 256>>>(off, csr, x, agg1, N);
    node0_prep<<<((size_t)N * 8 + 255) / 256, 256>>>(
        x, agg1, zhi_g, zlo_g, eps, W1f, b1, g1, be1, m1, v1, N);
    gin_node0_mma<<<nodeGrid, 256, MMA_SMEM_U32 * 4>>>(
        zhi_g, zlo_g, hh0, batch, pooled, w0prep,
        b1, g1, be1, m1, v1,
        b2, g2, be2, m2, v2, N);

    // ----- layers 1..7: bf16 gather -> split-bf16 z -> bf16x2 MMA MLP -----
    for (int i = 1; i < LL; ++i) {
        const __nv_bfloat162* hprev = (i & 1) ? hh0 : hh1;
        __nv_bfloat162* hout = (i & 1) ? hh1 : hh0;
        csr_agg_h<<<((size_t)N * 8 + 255) / 256, 256>>>(off, csr, hprev, zhi_g, zlo_g, eps + i, N);
        gin_node_mma<<<nodeGrid, 256, MMA_SMEM_U32 * 4>>>(
            zhi_g, zlo_g, hout, batch, pooled, i,
            wprep + (size_t)(i - 1) * 9216,
            b1 + i * 64, g1 + i * 64, be1 + i * 64, m1 + i * 64, v1 + i * 64,
            b2 + i * 64, g2 + i * 64, be2 + i * 64, m2 + i * 64, v2 + i * 64, N);
    }

    // ----- head -----
    classify_kernel<<<G, 64>>>(pooled, batch, N, lw1, lb1, lw2, lb2, (float*)d_out);
}

// round 16
// speedup vs baseline: 1.0348x; 1.0348x over previous
#include <cuda_runtime.h>
#include <cuda_bf16.h>
#include <math.h>

#define MAXN 100000
#define MAXE 1600000
#define MAXG 500
#define LL 8
#define BN_EPS 1e-5f

// ---------------- device scratch ----------------
__device__ __nv_bfloat162 g_hh[2][(size_t)MAXN * 32];  // bf16 features, ping-pong (128B rows)
__device__ uint4 g_zhi[(size_t)MAXN * 8];               // z hi split, 32 u32/node
__device__ uint4 g_zlo[(size_t)MAXN * 8];               // z lo split
__device__ float g_agg1[MAXN];                          // layer-0 scalar agg
__device__ float g_pooled[(size_t)MAXG * LL * 64];
__device__ unsigned g_wprep[7 * 9216];                  // split-transposed weights, smem layout
__device__ unsigned g_w0prep[4608];                     // layer-0 W2 split (hi|lo)
__device__ int g_deg[MAXN + 1];
__device__ int g_off[MAXN + 2];
__device__ int g_pos[MAXN + 1];
__device__ int g_csr[MAXE];
__device__ int g_bsum[1024];

// ---------------- helpers ----------------
__device__ __forceinline__ void bfsplit(float x, float y, unsigned& hi, unsigned& lo) {
    __nv_bfloat162 h = __floats2bfloat162_rn(x, y);
    float rx = x - __bfloat162float(h.x);
    float ry = y - __bfloat162float(h.y);
    __nv_bfloat162 l = __floats2bfloat162_rn(rx, ry);
    hi = *reinterpret_cast<unsigned*>(&h);
    lo = *reinterpret_cast<unsigned*>(&l);
}
__device__ __forceinline__ void mma16(float (&c)[4], unsigned a0, unsigned a1, unsigned a2, unsigned a3,
                                      unsigned b0, unsigned b1) {
    asm volatile("mma.sync.aligned.m16n8k16.row.col.f32.bf16.bf16.f32 "
                 "{%0,%1,%2,%3},{%4,%5,%6,%7},{%8,%9},{%0,%1,%2,%3};"
                 : "+f"(c[0]), "+f"(c[1]), "+f"(c[2]), "+f"(c[3])
                 : "r"(a0), "r"(a1), "r"(a2), "r"(a3), "r"(b0), "r"(b1));
}

// ============ CSR build ============
__global__ __launch_bounds__(256) void deg_count(const int* __restrict__ ei, int E, int* __restrict__ deg) {
    int e = blockIdx.x * 256 + threadIdx.x;
    if (e >= E) return;
    atomicAdd(&deg[ei[E + e]], 1);
}

__global__ __launch_bounds__(512) void chunk_sum(const int* __restrict__ deg, int n, int* __restrict__ bsum) {
    __shared__ int sh[512];
    int t = threadIdx.x;
    int i = blockIdx.x * 512 + t;
    sh[t] = (i < n) ? deg[i] : 0;
    __syncthreads();
#pragma unroll
    for (int s = 256; s > 0; s >>= 1) {
        if (t < s) sh[t] += sh[t + s];
        __syncthreads();
    }
    if (t == 0) bsum[blockIdx.x] = sh[0];
}

__global__ __launch_bounds__(1024) void scan_bsum(int* __restrict__ bsum, int nb) {
    __shared__ int sh[1024];
    int t = threadIdx.x;
    int v = (t < nb) ? bsum[t] : 0;
    sh[t] = v;
    __syncthreads();
    for (int d = 1; d < 1024; d <<= 1) {
        int add = (t >= d) ? sh[t - d] : 0;
        __syncthreads();
        sh[t] += add;
        __syncthreads();
    }
    if (t < nb) bsum[t] = sh[t] - v;   // exclusive
}

__global__ __launch_bounds__(512) void chunk_scan(const int* __restrict__ deg, int n,
                                                  const int* __restrict__ bsum,
                                                  int* __restrict__ off, int* __restrict__ pos) {
    __shared__ int sh[512];
    int t = threadIdx.x;
    int i = blockIdx.x * 512 + t;
    int v = (i < n) ? deg[i] : 0;
    sh[t] = v;
    __syncthreads();
    for (int d = 1; d < 512; d <<= 1) {
        int add = (t >= d) ? sh[t - d] : 0;
        __syncthreads();
        sh[t] += add;
        __syncthreads();
    }
    if (i < n) {
        int ex = sh[t] - v + bsum[blockIdx.x];
        off[i] = ex;
        pos[i] = ex;
    }
}

__global__ __launch_bounds__(256) void csr_scatter(const int* __restrict__ ei, int E,
                                                   int* __restrict__ pos, int* __restrict__ csr) {
    int e = blockIdx.x * 256 + threadIdx.x;
    if (e >= E) return;
    int src = ei[e];
    int dst = ei[E + e];
    int p = atomicAdd(&pos[dst], 1);
    csr[p] = src;
}

// ============ weight pre-transform (once per launch) ============
#define AS 36   // row pitch in u32 (32 data + 4 pad)

__global__ __launch_bounds__(128) void prep_weights(const float* __restrict__ W1r,
                                                    const float* __restrict__ W2all,
                                                    unsigned* __restrict__ wprep) {
    int layer = blockIdx.x;                    // 0..6 -> layers 1..7
    const float* W1 = W1r + (size_t)layer * 4096;
    const float* W2 = W2all + (size_t)(layer + 1) * 4096;
    unsigned* dst = wprep + (size_t)layer * 9216;
    for (int idx = threadIdx.x; idx < 2048; idx += 128) {
        int n = idx >> 5, k2 = idx & 31;
        int koff = k2 * 128 + n;
        unsigned hi, lo;
        bfsplit(W1[koff], W1[koff + 64], hi, lo);
        dst[n * AS + k2] = hi;
        dst[2304 + n * AS + k2] = lo;
        bfsplit(W2[koff], W2[koff + 64], hi, lo);
        dst[4608 + n * AS + k2] = hi;
        dst[6912 + n * AS + k2] = lo;
    }
}

__global__ __launch_bounds__(128) void prep_w0(const float* __restrict__ W2all,
                                               unsigned* __restrict__ w0prep) {
    const float* W2 = W2all;   // layer 0
    for (int idx = threadIdx.x; idx < 2048; idx += 128) {
        int n = idx >> 5, k2 = idx & 31;
        int koff = k2 * 128 + n;
        unsigned hi, lo;
        bfsplit(W2[koff], W2[koff + 64], hi, lo);
        w0prep[n * AS + k2] = hi;
        w0prep[2304 + n * AS + k2] = lo;
    }
}

// ============ CSR aggregation (bf16 rows -> split-bf16 z) ============
__device__ __forceinline__ void addrow_u(uint4 v, float* acc) {
    acc[0] += __uint_as_float(v.x << 16);
    acc[1] += __uint_as_float(v.x & 0xffff0000u);
    acc[2] += __uint_as_float(v.y << 16);
    acc[3] += __uint_as_float(v.y & 0xffff0000u);
    acc[4] += __uint_as_float(v.z << 16);
    acc[5] += __uint_as_float(v.z & 0xffff0000u);
    acc[6] += __uint_as_float(v.w << 16);
    acc[7] += __uint_as_float(v.w & 0xffff0000u);
}

// 8 threads per node, each thread covers 8 contiguous features (16B).
__global__ __launch_bounds__(256) void csr_agg_h(const int* __restrict__ off, const int* __restrict__ csr,
                                                 const __nv_bfloat162* __restrict__ hh,
                                                 uint4* __restrict__ zhi_g, uint4* __restrict__ zlo_g,
                                                 const float* __restrict__ eps, int N) {
    int t = blockIdx.x * 256 + threadIdx.x;
    int n = t >> 3;
    if (n >= N) return;
    int q = t & 7;
    const uint4* hq = reinterpret_cast<const uint4*>(hh) + q;
    float acc[8];
#pragma unroll
    for (int j = 0; j < 8; ++j) acc[j] = 0.f;
    int b = off[n], e = off[n + 1];
    int i = b;
    for (; i + 8 <= e; i += 8) {
        int idx[8];
#pragma unroll
        for (int u = 0; u < 8; ++u) idx[u] = __ldg(&csr[i + u]);
        uint4 v[8];
#pragma unroll
        for (int u = 0; u < 8; ++u) v[u] = hq[idx[u] * 8];
#pragma unroll
        for (int u = 0; u < 8; ++u) addrow_u(v[u], acc);
    }
    for (; i + 4 <= e; i += 4) {
        int i0 = __ldg(&csr[i]);
        int i1 = __ldg(&csr[i + 1]);
        int i2 = __ldg(&csr[i + 2]);
        int i3 = __ldg(&csr[i + 3]);
        uint4 v0 = hq[i0 * 8];
        uint4 v1 = hq[i1 * 8];
        uint4 v2 = hq[i2 * 8];
        uint4 v3 = hq[i3 * 8];
        addrow_u(v0, acc);
        addrow_u(v1, acc);
        addrow_u(v2, acc);
        addrow_u(v3, acc);
    }
    for (; i < e; ++i) addrow_u(hq[__ldg(&csr[i]) * 8], acc);

    float ev = 1.0f + eps[0];
    uint4 sv = hq[n * 8];
    float o[8];
    o[0] = fmaf(ev, __uint_as_float(sv.x << 16),          acc[0]);
    o[1] = fmaf(ev, __uint_as_float(sv.x & 0xffff0000u),  acc[1]);
    o[2] = fmaf(ev, __uint_as_float(sv.y << 16),          acc[2]);
    o[3] = fmaf(ev, __uint_as_float(sv.y & 0xffff0000u),  acc[3]);
    o[4] = fmaf(ev, __uint_as_float(sv.z << 16),          acc[4]);
    o[5] = fmaf(ev, __uint_as_float(sv.z & 0xffff0000u),  acc[5]);
    o[6] = fmaf(ev, __uint_as_float(sv.w << 16),          acc[6]);
    o[7] = fmaf(ev, __uint_as_float(sv.w & 0xffff0000u),  acc[7]);

    uint4 hi4, lo4;
    bfsplit(o[0], o[1], hi4.x, lo4.x);
    bfsplit(o[2], o[3], hi4.y, lo4.y);
    bfsplit(o[4], o[5], hi4.z, lo4.z);
    bfsplit(o[6], o[7], hi4.w, lo4.w);
    zhi_g[(size_t)n * 8 + q] = hi4;
    zlo_g[(size_t)n * 8 + q] = lo4;
}

// scalar features (layer 0)
__global__ __launch_bounds__(256) void csr_agg1(const int* __restrict__ off, const int* __restrict__ csr,
                                                const float* __restrict__ x, float* __restrict__ agg, int N) {
    int n = blockIdx.x * 256 + threadIdx.x;
    if (n >= N) return;
    int b = off[n], e = off[n + 1];
    float s = 0.f;
    int i = b;
    for (; i + 4 <= e; i += 4) {
        float v0 = x[__ldg(&csr[i])];
        float v1 = x[__ldg(&csr[i + 1])];
        float v2 = x[__ldg(&csr[i + 2])];
        float v3 = x[__ldg(&csr[i + 3])];
        s += (v0 + v1) + (v2 + v3);
    }
    for (; i < e; ++i) s += x[__ldg(&csr[i])];
    agg[n] = s;
}

// layer 0 MLP1+BN1: 8 threads/node, thread q handles features [8q, 8q+8)
__global__ __launch_bounds__(256) void node0_prep(
        const float* __restrict__ x, const float* __restrict__ agg,
        uint4* __restrict__ zhi_g, uint4* __restrict__ zlo_g,
        const float* __restrict__ eps, const float* __restrict__ W1f,
        const float* __restrict__ b1, const float* __restrict__ g1,
        const float* __restrict__ be1, const float* __restrict__ m1,
        const float* __restrict__ v1, int N) {
    int t = blockIdx.x * 256 + threadIdx.x;
    int n = t >> 3;
    if (n >= N) return;
    int q = t & 7;
    float ev = 1.0f + eps[0];
    float z = fmaf(ev, x[n], agg[n]);
    float o[8];
#pragma unroll
    for (int u = 0; u < 8; ++u) {
        int j = q * 8 + u;
        float s1 = __ldg(&g1[j]) * rsqrtf(__ldg(&v1[j]) + BN_EPS);
        float t1 = fmaf(-__ldg(&m1[j]), s1, __ldg(&be1[j]));
        float y = fmaxf(fmaf(z, __ldg(&W1f[j]), __ldg(&b1[j])), 0.f);
        o[u] = fmaf(y, s1, t1);
    }
    uint4 hi4, lo4;
    bfsplit(o[0], o[1], hi4.x, lo4.x);
    bfsplit(o[2], o[3], hi4.y, lo4.y);
    bfsplit(o[4], o[5], hi4.z, lo4.z);
    bfsplit(o[6], o[7], hi4.w, lo4.w);
    zhi_g[(size_t)n * 8 + q] = hi4;
    zlo_g[(size_t)n * 8 + q] = lo4;
}

// ============ BN params ============
__device__ __forceinline__ void load_bn_params(float* prm, int tid,
        const float* b1, const float* g1, const float* be1, const float* m1, const float* v1,
        const float* b2, const float* g2, const float* be2, const float* m2, const float* v2) {
    if (tid < 64) {
        float s1 = g1[tid] * rsqrtf(v1[tid] + BN_EPS);
        prm[tid]       = b1[tid];
        prm[64 + tid]  = s1;
        prm[128 + tid] = fmaf(-m1[tid], s1, be1[tid]);
        float s2 = g2[tid] * rsqrtf(v2[tid] + BN_EPS);
        prm[192 + tid] = b2[tid];
        prm[256 + tid] = s2;
        prm[320 + tid] = fmaf(-m2[tid], s2, be2[tid]);
    }
}

// ============ tensor-core node MLP, bf16x2 split 3-term, 256 nodes/block ============
#define OFF_W1HI 0
#define OFF_W1LO 2304
#define OFF_W2HI 4608
#define OFF_W2LO 6912
#define OFF_ZHI  9216
#define OFF_ZLO  18432
#define OFF_PRM  27648
#define MMA_SMEM_U32 (27648 + 384)

__device__ __forceinline__ void warp_gemm_bf(const unsigned* __restrict__ Whi,
                                             const unsigned* __restrict__ Wlo,
                                             const unsigned* __restrict__ zhi,
                                             const unsigned* __restrict__ zlo,
                                             int warp, int lane, float acc[2][8][4]) {
    int tig = lane & 3;
    int grp = lane >> 2;
#pragma unroll
    for (int kk = 0; kk < 4; ++kk) {
        int k2a = kk * 8 + tig;
        int k2b = kk * 8 + 4 + tig;
        unsigned bh[8][2], bl[8][2];
#pragma unroll
        for (int nt = 0; nt < 8; ++nt) {
            int n = nt * 8 + grp;
            bh[nt][0] = Whi[n * AS + k2a];
            bh[nt][1] = Whi[n * AS + k2b];
            bl[nt][0] = Wlo[n * AS + k2a];
            bl[nt][1] = Wlo[n * AS + k2b];
        }
#pragma unroll
        for (int mt = 0; mt < 2; ++mt) {
            int r0 = warp * 32 + mt * 16 + grp;
            unsigned ah0 = zhi[r0 * AS + k2a];
            unsigned ah1 = zhi[(r0 + 8) * AS + k2a];
            unsigned ah2 = zhi[r0 * AS + k2b];
            unsigned ah3 = zhi[(r0 + 8) * AS + k2b];
            unsigned al0 = zlo[r0 * AS + k2a];
            unsigned al1 = zlo[(r0 + 8) * AS + k2a];
            unsigned al2 = zlo[r0 * AS + k2b];
            unsigned al3 = zlo[(r0 + 8) * AS + k2b];
#pragma unroll
            for (int nt = 0; nt < 8; ++nt) {
                mma16(acc[mt][nt], ah0, ah1, ah2, ah3, bh[nt][0], bh[nt][1]);
                mma16(acc[mt][nt], ah0, ah1, ah2, ah3, bl[nt][0], bl[nt][1]);
                mma16(acc[mt][nt], al0, al1, al2, al3, bh[nt][0], bh[nt][1]);
            }
        }
    }
}

// shared epilogue: BN2 + bf16 store + pooled RED (warp-prereduced atomics)
__device__ __forceinline__ void mma_epilogue(float acc[2][8][4], const float* prm,
                                             const int* sh_b, int n0, int warp, int lane,
                                             int tig, int grp, int N, int layer,
                                             __nv_bfloat162* houth, float* pooled) {
    int gme = sh_b[warp * 32 + lane];
    int g0 = __shfl_sync(0xffffffffu, gme, 0);
    bool uni = __all_sync(0xffffffffu, gme == g0) && (g0 >= 0);

#pragma unroll
    for (int nt = 0; nt < 8; ++nt) {
        int j = nt * 8 + 2 * tig;
        float b2a = prm[192 + j], b2b = prm[192 + j + 1];
        float s2a = prm[256 + j], s2b = prm[256 + j + 1];
        float t2a = prm[320 + j], t2b = prm[320 + j + 1];
        int jc = j >> 1;
        float p0 = 0.f, p1 = 0.f;
#pragma unroll
        for (int mt = 0; mt < 2; ++mt) {
            float* C = acc[mt][nt];
            int row = warp * 32 + mt * 16 + grp;
            int n = n0 + row;
            if (n < N) {
                float o0 = fmaf(fmaxf(C[0] + b2a, 0.f), s2a, t2a);
                float o1 = fmaf(fmaxf(C[1] + b2b, 0.f), s2b, t2b);
                houth[(size_t)n * 32 + jc] = __floats2bfloat162_rn(o0, o1);
                if (uni) { p0 += o0; p1 += o1; }
                else {
                    float* pp = pooled + (size_t)sh_b[row] * 512 + layer * 64 + j;
                    atomicAdd(pp, o0);
                    atomicAdd(pp + 1, o1);
                }
            }
            if (n + 8 < N) {
                float o2 = fmaf(fmaxf(C[2] + b2a, 0.f), s2a, t2a);
                float o3 = fmaf(fmaxf(C[3] + b2b, 0.f), s2b, t2b);
                houth[(size_t)(n + 8) * 32 + jc] = __floats2bfloat162_rn(o2, o3);
                if (uni) { p0 += o2; p1 += o3; }
                else {
                    float* pp = pooled + (size_t)sh_b[row + 8] * 512 + layer * 64 + j;
                    atomicAdd(pp, o2);
                    atomicAdd(pp + 1, o3);
                }
            }
        }
        if (uni) {
            p0 += __shfl_xor_sync(0xffffffffu, p0, 4);
            p1 += __shfl_xor_sync(0xffffffffu, p1, 4);
            p0 += __shfl_xor_sync(0xffffffffu, p0, 8);
            p1 += __shfl_xor_sync(0xffffffffu, p1, 8);
            p0 += __shfl_xor_sync(0xffffffffu, p0, 16);
            p1 += __shfl_xor_sync(0xffffffffu, p1, 16);
            if (grp == 0) {
                float* pp = pooled + (size_t)g0 * 512 + layer * 64 + j;
                atomicAdd(pp, p0);
                atomicAdd(pp + 1, p1);
            }
        }
    }
}

__global__ __launch_bounds__(256) void gin_node_mma(
        const uint4* __restrict__ zhi_g, const uint4* __restrict__ zlo_g,
        __nv_bfloat162* __restrict__ houth,
        const int* __restrict__ batch, float* __restrict__ pooled, int layer,
        const unsigned* __restrict__ wprep,
        const float* __restrict__ b1,
        const float* __restrict__ g1, const float* __restrict__ be1,
        const float* __restrict__ m1, const float* __restrict__ v1,
        const float* __restrict__ b2,
        const float* __restrict__ g2, const float* __restrict__ be2,
        const float* __restrict__ m2, const float* __restrict__ v2, int N) {
    extern __shared__ unsigned smu[];
    unsigned* W1hi = smu + OFF_W1HI;
    unsigned* W1lo = smu + OFF_W1LO;
    unsigned* W2hi = smu + OFF_W2HI;
    unsigned* W2lo = smu + OFF_W2LO;
    unsigned* zhi  = smu + OFF_ZHI;
    unsigned* zlo  = smu + OFF_ZLO;
    float* prm = reinterpret_cast<float*>(smu + OFF_PRM);
    __shared__ int sh_b[256];
    int tid = threadIdx.x;
    int warp = tid >> 5, lane = tid & 31;
    int tig = lane & 3, grp = lane >> 2;

    {
        const uint4* wsrc = reinterpret_cast<const uint4*>(wprep);
        uint4* wdst = reinterpret_cast<uint4*>(smu);
#pragma unroll
        for (int i = tid; i < 2304; i += 256) wdst[i] = wsrc[i];
    }
    load_bn_params(prm, tid, b1, g1, be1, m1, v1, b2, g2, be2, m2, v2);

    int n0 = blockIdx.x * 256;
    sh_b[tid] = (n0 + tid < N) ? batch[n0 + tid] : -1;

    for (int i2 = tid; i2 < 2048; i2 += 256) {
        int row = i2 >> 3, qq = i2 & 7;
        uint4 h4 = make_uint4(0, 0, 0, 0), l4 = make_uint4(0, 0, 0, 0);
        if (n0 + row < N) {
            h4 = zhi_g[(size_t)n0 * 8 + i2];
            l4 = zlo_g[(size_t)n0 * 8 + i2];
        }
        *reinterpret_cast<uint4*>(&zhi[row * AS + qq * 4]) = h4;
        *reinterpret_cast<uint4*>(&zlo[row * AS + qq * 4]) = l4;
    }
    __syncthreads();

    float acc[2][8][4];
#pragma unroll
    for (int mt = 0; mt < 2; ++mt)
#pragma unroll
        for (int nt = 0; nt < 8; ++nt)
#pragma unroll
            for (int p = 0; p < 4; ++p) acc[mt][nt][p] = 0.f;

    warp_gemm_bf(W1hi, W1lo, zhi, zlo, warp, lane, acc);

    // BN1 + ReLU -> back into zs (warp-private rows), zero acc
#pragma unroll
    for (int nt = 0; nt < 8; ++nt) {
        int j = nt * 8 + 2 * tig;
        float b1a = prm[j],       b1b = prm[j + 1];
        float s1a = prm[64 + j],  s1b = prm[64 + j + 1];
        float t1a = prm[128 + j], t1b = prm[128 + j + 1];
        int k2 = nt * 4 + tig;
#pragma unroll
        for (int mt = 0; mt < 2; ++mt) {
            float* C = acc[mt][nt];
            int row = warp * 32 + mt * 16 + grp;
            float y0 = fmaf(fmaxf(C[0] + b1a, 0.f), s1a, t1a);
            float y1 = fmaf(fmaxf(C[1] + b1b, 0.f), s1b, t1b);
            float y2 = fmaf(fmaxf(C[2] + b1a, 0.f), s1a, t1a);
            float y3 = fmaf(fmaxf(C[3] + b1b, 0.f), s1b, t1b);
            unsigned hi, lo;
            bfsplit(y0, y1, hi, lo);
            zhi[row * AS + k2] = hi;
            zlo[row * AS + k2] = lo;
            bfsplit(y2, y3, hi, lo);
            zhi[(row + 8) * AS + k2] = hi;
            zlo[(row + 8) * AS + k2] = lo;
            C[0] = C[1] = C[2] = C[3] = 0.f;
        }
    }
    __syncwarp();

    warp_gemm_bf(W2hi, W2lo, zhi, zlo, warp, lane, acc);
    mma_epilogue(acc, prm, sh_b, n0, warp, lane, tig, grp, N, layer, houth, pooled);
}

// layer 0 node kernel: GEMM2-only (z buffers already hold BN1(ReLU(MLP1)))
__global__ __launch_bounds__(256) void gin_node0_mma(
        const uint4* __restrict__ zhi_g, const uint4* __restrict__ zlo_g,
        __nv_bfloat162* __restrict__ houth,
        const int* __restrict__ batch, float* __restrict__ pooled,
        const unsigned* __restrict__ w0prep,
        const float* __restrict__ b1,
        const float* __restrict__ g1, const float* __restrict__ be1,
        const float* __restrict__ m1, const float* __restrict__ v1,
        const float* __restrict__ b2,
        const float* __restrict__ g2, const float* __restrict__ be2,
        const float* __restrict__ m2, const float* __restrict__ v2, int N) {
    extern __shared__ unsigned smu[];
    unsigned* W2hi = smu + OFF_W2HI;
    unsigned* W2lo = smu + OFF_W2LO;
    unsigned* zhi  = smu + OFF_ZHI;
    unsigned* zlo  = smu + OFF_ZLO;
    float* prm = reinterpret_cast<float*>(smu + OFF_PRM);
    __shared__ int sh_b[256];
    int tid = threadIdx.x;
    int warp = tid >> 5, lane = tid & 31;
    int tig = lane & 3, grp = lane >> 2;

    {
        const uint4* wsrc = reinterpret_cast<const uint4*>(w0prep);
        uint4* wdst = reinterpret_cast<uint4*>(smu + OFF_W2HI);
#pragma unroll
        for (int i = tid; i < 1152; i += 256) wdst[i] = wsrc[i];
    }
    load_bn_params(prm, tid, b1, g1, be1, m1, v1, b2, g2, be2, m2, v2);

    int n0 = blockIdx.x * 256;
    sh_b[tid] = (n0 + tid < N) ? batch[n0 + tid] : -1;

    for (int i2 = tid; i2 < 2048; i2 += 256) {
        int row = i2 >> 3, qq = i2 & 7;
        uint4 h4 = make_uint4(0, 0, 0, 0), l4 = make_uint4(0, 0, 0, 0);
        if (n0 + row < N) {
            h4 = zhi_g[(size_t)n0 * 8 + i2];
            l4 = zlo_g[(size_t)n0 * 8 + i2];
        }
        *reinterpret_cast<uint4*>(&zhi[row * AS + qq * 4]) = h4;
        *reinterpret_cast<uint4*>(&zlo[row * AS + qq * 4]) = l4;
    }
    __syncthreads();

    float acc[2][8][4];
#pragma unroll
    for (int mt = 0; mt < 2; ++mt)
#pragma unroll
        for (int nt = 0; nt < 8; ++nt)
#pragma unroll
            for (int p = 0; p < 4; ++p) acc[mt][nt][p] = 0.f;

    warp_gemm_bf(W2hi, W2lo, zhi, zlo, warp, lane, acc);
    mma_epilogue(acc, prm, sh_b, n0, warp, lane, tig, grp, N, 0, houth, pooled);
}

// ---------------- classifier head ----------------
__device__ __forceinline__ int lbound(const int* __restrict__ a, int n, int v) {
    int lo = 0, hi = n;
    while (lo < hi) {
        int mid = (lo + hi) >> 1;
        if (a[mid] < v) lo = mid + 1; else hi = mid;
    }
    return lo;
}

__global__ __launch_bounds__(64) void classify_kernel(
        const float* __restrict__ pooled, const int* __restrict__ batch, int N,
        const float* __restrict__ lw1, const float* __restrict__ lb1,
        const float* __restrict__ lw2, const float* __restrict__ lb2,
        float* __restrict__ out) {
    __shared__ float ps[512];
    __shared__ float hid[64];
    __shared__ float lg[3];
    __shared__ float inv;
    int g = blockIdx.x;
    int tid = threadIdx.x;
    if (tid == 0) {
        int a = lbound(batch, N, g);
        int b = lbound(batch, N, g + 1);
        int c = b - a;
        inv = 1.0f / (float)(c > 1 ? c : 1);
    }
    __syncthreads();
    for (int k = tid; k < 512; k += 64) ps[k] = pooled[(size_t)g * 512 + k] * inv;
    __syncthreads();
    float acc = lb1[tid];
#pragma unroll 8
    for (int k = 0; k < 512; ++k) acc = fmaf(ps[k], lw1[k * 64 + tid], acc);
    hid[tid] = fmaxf(acc, 0.f);
    __syncthreads();
    if (tid < 3) {
        float s = lb2[tid];
#pragma unroll
        for (int j = 0; j < 64; ++j) s = fmaf(hid[j], lw2[j * 3 + tid], s);
        lg[tid] = s;
    }
    __syncthreads();
    if (tid == 0) {
        float m = fmaxf(lg[0], fmaxf(lg[1], lg[2]));
        float e = expf(lg[0] - m) + expf(lg[1] - m) + expf(lg[2] - m);
        float lse = m + logf(e);
        out[g * 3 + 0] = lg[0] - lse;
        out[g * 3 + 1] = lg[1] - lse;
        out[g * 3 + 2] = lg[2] - lse;
    }
}

// ---------------- launcher ----------------
extern "C" void kernel_launch(void* const* d_in, const int* in_sizes, int n_in,
                              void* d_out, int out_size) {
    const float* x     = (const float*)d_in[0];
    const int*   ei    = (const int*)d_in[1];
    const int*   batch = (const int*)d_in[2];
    int bi = (in_sizes[3] == 1) ? 4 : 3;
    const float* eps  = (const float*)d_in[bi + 0];
    const float* W1f  = (const float*)d_in[bi + 1];
    const float* W1r  = (const float*)d_in[bi + 2];
    const float* b1   = (const float*)d_in[bi + 3];
    const float* g1   = (const float*)d_in[bi + 4];
    const float* be1  = (const float*)d_in[bi + 5];
    const float* m1   = (const float*)d_in[bi + 6];
    const float* v1   = (const float*)d_in[bi + 7];
    const float* W2   = (const float*)d_in[bi + 8];
    const float* b2   = (const float*)d_in[bi + 9];
    const float* g2   = (const float*)d_in[bi + 10];
    const float* be2  = (const float*)d_in[bi + 11];
    const float* m2   = (const float*)d_in[bi + 12];
    const float* v2   = (const float*)d_in[bi + 13];
    const float* lw1  = (const float*)d_in[bi + 14];
    const float* lb1  = (const float*)d_in[bi + 15];
    const float* lw2  = (const float*)d_in[bi + 16];
    const float* lb2  = (const float*)d_in[bi + 17];

    int N = in_sizes[0];
    int E = in_sizes[1] / 2;
    int G = out_size / 3;
    if (N > MAXN) N = MAXN;
    if (E > MAXE) E = MAXE;
    if (G > MAXG) G = MAXG;

    __nv_bfloat162 *hh0, *hh1;
    uint4 *zhi_g, *zlo_g;
    float *agg1, *pooled;
    unsigned *wprep, *w0prep;
    int *deg, *off, *pos, *csr, *bsum;
    cudaGetSymbolAddress((void**)&hh0, g_hh);
    hh1 = hh0 + (size_t)MAXN * 32;
    cudaGetSymbolAddress((void**)&zhi_g, g_zhi);
    cudaGetSymbolAddress((void**)&zlo_g, g_zlo);
    cudaGetSymbolAddress((void**)&agg1, g_agg1);
    cudaGetSymbolAddress((void**)&pooled, g_pooled);
    cudaGetSymbolAddress((void**)&wprep, g_wprep);
    cudaGetSymbolAddress((void**)&w0prep, g_w0prep);
    cudaGetSymbolAddress((void**)&deg, g_deg);
    cudaGetSymbolAddress((void**)&off, g_off);
    cudaGetSymbolAddress((void**)&pos, g_pos);
    cudaGetSymbolAddress((void**)&csr, g_csr);
    cudaGetSymbolAddress((void**)&bsum, g_bsum);

    cudaFuncSetAttribute(gin_node_mma, cudaFuncAttributeMaxDynamicSharedMemorySize,
                         MMA_SMEM_U32 * 4);
    cudaFuncSetAttribute(gin_node0_mma, cudaFuncAttributeMaxDynamicSharedMemorySize,
                         MMA_SMEM_U32 * 4);

    int nodeGrid = (N + 255) / 256;
    int edgeGrid = (E + 255) / 256;
    int nScan = N + 1;
    int nb = (nScan + 511) / 512;

    // ----- CSR build + pooled clear + weight prep -----
    cudaMemsetAsync(deg, 0, (size_t)nScan * sizeof(int));
    cudaMemsetAsync(pooled, 0, (size_t)G * 512 * sizeof(float));
    prep_weights<<<7, 128>>>(W1r, W2, wprep);
    prep_w0<<<1, 128>>>(W2, w0prep);
    deg_count<<<edgeGrid, 256>>>(ei, E, deg);
    chunk_sum<<<nb, 512>>>(deg, nScan, bsum);
    scan_bsum<<<1, 1024>>>(bsum, nb);
    chunk_scan<<<nb, 512>>>(deg, nScan, bsum, off, pos);
    csr_scatter<<<edgeGrid, 256>>>(ei, E, pos, csr);

    // ----- layer 0 (scalar input) -----
    csr_agg1<<<(N + 255) / 256, 256>>>(off, csr, x, agg1, N);
    node0_prep<<<((size_t)N * 8 + 255) / 256, 256>>>(
        x, agg1, zhi_g, zlo_g, eps, W1f, b1, g1, be1, m1, v1, N);
    gin_node0_mma<<<nodeGrid, 256, MMA_SMEM_U32 * 4>>>(
        zhi_g, zlo_g, hh0, batch, pooled, w0prep,
        b1, g1, be1, m1, v1,
        b2, g2, be2, m2, v2, N);

    // ----- layers 1..7: bf16 gather -> split-bf16 z -> bf16x2 MMA MLP -----
    for (int i = 1; i < LL; ++i) {
        const __nv_bfloat162* hprev = (i & 1) ? hh0 : hh1;
        __nv_bfloat162* hout = (i & 1) ? hh1 : hh0;
        csr_agg_h<<<((size_t)N * 8 + 255) / 256, 256>>>(off, csr, hprev, zhi_g, zlo_g, eps + i, N);
        gin_node_mma<<<nodeGrid, 256, MMA_SMEM_U32 * 4>>>(
            zhi_g, zlo_g, hout, batch, pooled, i,
            wprep + (size_t)(i - 1) * 9216,
            b1 + i * 64, g1 + i * 64, be1 + i * 64, m1 + i * 64, v1 + i * 64,
            b2 + i * 64, g2 + i * 64, be2 + i * 64, m2 + i * 64, v2 + i * 64, N);
    }

    // ----- head -----
    classify_kernel<<<G, 64>>>(pooled, batch, N, lw1, lb1, lw2, lb2, (float*)d_out);
}